// round 9
// baseline (speedup 1.0000x reference)
#include <cuda_runtime.h>
#include <cuda_fp16.h>
#include <stdint.h>

#define NT 4
#define P0 100
#define P1C 100
#define P2C 100

// W12 scratch, per (t,i1,i2) slice as TWO mma.m16n8k16 A-fragments
// (k = r1 0..15 / 16..31). Slice = 1KB. 41 MB -> L2-resident.
__device__ __align__(16) __half g_W12[(size_t)NT * P1C * P2C * 512];

// c0 as fp16 B-fragments: per (t,i0) slice, lane l holds uint4
// {b0_f0, b1_f0, b0_f1, b1_f1}. B[k=r1][n=q0], cols 4..7 zero. 204.8KB.
__device__ uint4 g_c0f[(size_t)NT * P0 * 32];

// ---- Blackwell packed fp32 helpers -----------------------------------------
#define FMA_F32X2(d, a, b, c) \
    asm("fma.rn.f32x2 %0, %1, %2, %3;" : "=l"(d) : "l"(a), "l"(b), "l"(c))
#define ADD_F32X2_(d, a, b) \
    asm("add.rn.f32x2 %0, %1, %2;" : "=l"(d) : "l"(a), "l"(b))

__device__ __forceinline__ unsigned long long pack2(float lo, float hi) {
    unsigned long long r;
    asm("mov.b64 %0, {%1, %2};" : "=l"(r) : "f"(lo), "f"(hi));
    return r;
}
__device__ __forceinline__ float2 unpack2(unsigned long long v) {
    float2 f;
    asm("mov.b64 {%0, %1}, %2;" : "=f"(f.x), "=f"(f.y) : "l"(v));
    return f;
}
// r = {hi:lo} packed fp16x2
__device__ __forceinline__ unsigned pack_h2(float lo, float hi) {
    unsigned r;
    asm("cvt.rn.f16x2.f32 %0, %1, %2;" : "=r"(r) : "f"(hi), "f"(lo));
    return r;
}

// c2t skewed layout: [q2][i2'][r2] with +8-float skew per q2 -> the four
// q2-broadcast-groups hit bank offsets {0,32,64,96}B -> conflict-free LDS.128.
#define C2T_Q2_STRIDE (50 * 32 + 8)   // 1608 floats
// c1 staging: [row=(r1,q1) 128][32 + 4 pad] floats (row stride 144B).
#define C1S_ROW 36

// ---------------------------------------------------------------------------
// Kernel 1: W12 fragments for one i2-half. Grid 400 = (t, i1), 256 threads =
// (m = tid&15, kp = tid>>4); thread computes W[m][2kp], W[m][2kp+1] = one
// half2 A-reg. c1 staged coalesced through padded smem, then hoisted+packed
// into registers; c2 half-table transposed+skewed in smem.
// ---------------------------------------------------------------------------
__global__ __launch_bounds__(256) void tt_precompute_kernel(
        const float* __restrict__ c1g, const float* __restrict__ c2g,
        int i2half) {
    int b = blockIdx.x;
    int tid = threadIdx.x;
    int t  = b / P1C;
    int i1 = b - t * P1C;
    int i2lo = i2half * 50;

    __shared__ __align__(16) float c2t[4 * C2T_Q2_STRIDE];   // ~25.7KB
    __shared__ __align__(16) float c1s[128 * C1S_ROW];       // 18.4KB

    int m  = tid & 15;                          // output m (q1,q2)
    int kp = tid >> 4;                          // r1 pair: r1 = 2kp, 2kp+1
    int q1 = m >> 2, q2 = m & 3;

    // Stage c1 slice (4096 floats) coalesced into padded smem.
    const float* c1 = c1g + (size_t)(t * P1C + i1) * 4096;   // [(r1,q1)][r2]
    #pragma unroll
    for (int pass = 0; pass < 16; pass++) {
        int idx = pass * 256 + tid;
        c1s[(idx >> 5) * C1S_ROW + (idx & 31)] = c1[idx];
    }

    // Transposed+skewed c2 half-table: c2t[q2][i2'][r2] = c2[i2lo+i2'][r2][q2]
    const float* c2base = c2g + ((size_t)t * P2C + i2lo) * 128;
    for (int idx = tid; idx < 50 * 128; idx += 256) {
        int i2p = idx >> 7;
        int rr  = (idx >> 2) & 31;
        int qq  = idx & 3;
        c2t[qq * C2T_Q2_STRIDE + i2p * 32 + rr] = c2base[idx];
    }
    __syncthreads();

    // Hoist + pack this thread's two c1 rows (r1 = 2kp, 2kp+1) from smem.
    const float4* rA = (const float4*)(c1s + (8 * kp + q1) * C1S_ROW);
    const float4* rB = (const float4*)(c1s + (8 * kp + 4 + q1) * C1S_ROW);
    unsigned long long PA[8][2], PB[8][2];
    #pragma unroll
    for (int k = 0; k < 8; k++) {
        float4 a = rA[k]; PA[k][0] = pack2(a.x, a.y); PA[k][1] = pack2(a.z, a.w);
        float4 c = rB[k]; PB[k][0] = pack2(c.x, c.y); PB[k][1] = pack2(c.z, c.w);
    }

    // Fragment destination for this thread's half2.
    int frag   = kp >> 3;
    int lane16 = (m & 7) * 4 + (kp & 3);
    int reg    = ((m >> 3) & 1) + (((kp >> 2) & 1) << 1);
    unsigned soff = frag * 512 + lane16 * 16 + reg * 4;
    char* Wt = (char*)g_W12 + ((size_t)(t * P1C + i1) * P2C + i2lo) * 1024;

    const float* c2q = c2t + q2 * C2T_Q2_STRIDE;
    for (int i2p = 0; i2p < 50; i2p++) {
        const ulonglong2* sp = (const ulonglong2*)(c2q + i2p * 32);
        unsigned long long a0 = 0, a1 = 0, b0 = 0, b1 = 0;
        #pragma unroll
        for (int k = 0; k < 8; k++) {
            ulonglong2 s = sp[k];
            FMA_F32X2(a0, PA[k][0], s.x, a0);
            FMA_F32X2(a1, PA[k][1], s.y, a1);
            FMA_F32X2(b0, PB[k][0], s.x, b0);
            FMA_F32X2(b1, PB[k][1], s.y, b1);
        }
        ADD_F32X2_(a0, a0, a1);                      // packed merges (free unpack)
        ADD_F32X2_(b0, b0, b1);
        float2 f0 = unpack2(a0), f1 = unpack2(b0);
        *(unsigned*)(Wt + i2p * 1024 + soff) = pack_h2(f0.x + f0.y, f1.x + f1.y);
    }
}

// ---------------------------------------------------------------------------
// Kernel 1b: c0 -> fp16 B-fragments. One warp per (t,i0) slice.
// ---------------------------------------------------------------------------
__global__ void tt_c0frag_kernel(const float* __restrict__ c0g) {
    int slice = blockIdx.x * (blockDim.x >> 5) + (threadIdx.x >> 5);
    if (slice >= NT * P0) return;
    int lane = threadIdx.x & 31;
    int g = lane >> 2, j = lane & 3;
    uint4 v = make_uint4(0u, 0u, 0u, 0u);
    if (g < 4) {
        const float* row = c0g + (size_t)slice * 128 + g * 32 + 2 * j;
        float2 p0 = *(const float2*)(row);
        float2 p1 = *(const float2*)(row + 8);
        float2 p2 = *(const float2*)(row + 16);
        float2 p3 = *(const float2*)(row + 24);
        v.x = pack_h2(p0.x, p0.y);
        v.y = pack_h2(p1.x, p1.y);
        v.z = pack_h2(p2.x, p2.y);
        v.w = pack_h2(p3.x, p3.y);
    }
    g_c0f[(size_t)slice * 32 + lane] = v;
}

// ---------------------------------------------------------------------------
// Kernel 2: per-bag lookup + pool via HMMA. One warp per bag.
// Per lookup: 1 shfl + 3 coalesced LDG.128 + 2 mma.m16n8k16 (f32 accum).
// At the chip LTS cap (~1KB W12 gather per lookup) -- algorithmic floor.
// ---------------------------------------------------------------------------
__global__ void tt_lookup_kernel(const int* __restrict__ indices,
                                 const int* __restrict__ offsets,
                                 float* __restrict__ out,
                                 int B, int bags_per_table) {
    int bag = (int)((blockIdx.x * (size_t)blockDim.x + threadIdx.x) >> 5);
    if (bag >= B) return;
    int lane = threadIdx.x & 31;
    int g = lane >> 2, j = lane & 3;

    int t = bag / bags_per_table;
    int s = offsets[bag], e = offsets[bag + 1];

    const uint4* Wt = (const uint4*)(g_W12 + (size_t)t * P1C * P2C * 512);
    const uint4* Cf = g_c0f + (size_t)t * P0 * 32;

    float d0 = 0.f, d1 = 0.f, d2 = 0.f, d3 = 0.f;

    for (int base = s; base < e; base += 32) {
        int n = min(32, e - base);
        int idx = (base + lane < e) ? indices[base + lane] : 0;  // coalesced
        int i0  = idx / 10000;
        int rem = idx - i0 * 10000;
        int v   = rem | (i0 << 20);            // slice id (20b) | i0 (7b)

        for (int p = 0; p < n; p++) {
            int vp = __shfl_sync(0xffffffffu, v, p);
            const uint4* wb = Wt + (vp & 0xFFFFF) * 64;
            const uint4* cb = Cf + (vp >> 20) * 32;
            uint4 A0 = wb[lane];
            uint4 A1 = wb[32 + lane];
            uint4 Bf = cb[lane];
            asm volatile(
                "mma.sync.aligned.m16n8k16.row.col.f32.f16.f16.f32 "
                "{%0,%1,%2,%3}, {%4,%5,%6,%7}, {%8,%9}, {%0,%1,%2,%3};"
                : "+f"(d0), "+f"(d1), "+f"(d2), "+f"(d3)
                : "r"(A0.x), "r"(A0.y), "r"(A0.z), "r"(A0.w),
                  "r"(Bf.x), "r"(Bf.y));
            asm volatile(
                "mma.sync.aligned.m16n8k16.row.col.f32.f16.f16.f32 "
                "{%0,%1,%2,%3}, {%4,%5,%6,%7}, {%8,%9}, {%0,%1,%2,%3};"
                : "+f"(d0), "+f"(d1), "+f"(d2), "+f"(d3)
                : "r"(A1.x), "r"(A1.y), "r"(A1.z), "r"(A1.w),
                  "r"(Bf.z), "r"(Bf.w));
        }
    }

    // D[m][q0]: d0=(g,2j) d1=(g,2j+1) d2=(g+8,2j) d3=(g+8,2j+1);
    // out[bag][q0*16 + m]; only cols 0..3 valid -> lanes with j<2 write.
    if (j < 2) {
        float* ob = out + (size_t)bag * 64;
        ob[(2 * j) * 16 + g]         = d0;
        ob[(2 * j + 1) * 16 + g]     = d1;
        ob[(2 * j) * 16 + g + 8]     = d2;
        ob[(2 * j + 1) * 16 + g + 8] = d3;
    }
}

// ---------------------------------------------------------------------------
// 4 launches/iter so ncu (-s 5 -c 1) lands on precompute half B (idx 5).
// ---------------------------------------------------------------------------
extern "C" void kernel_launch(void* const* d_in, const int* in_sizes, int n_in,
                              void* d_out, int out_size) {
    const int* indices = (const int*)d_in[0];
    const int* offsets = (const int*)d_in[1];
    const float* c0 = (const float*)d_in[2];
    const float* c1 = (const float*)d_in[3];
    const float* c2 = (const float*)d_in[4];

    int B = in_sizes[1] - 1;
    int bags_per_table = B / NT;

    tt_precompute_kernel<<<NT * P1C, 256>>>(c1, c2, 0);
    tt_precompute_kernel<<<NT * P1C, 256>>>(c1, c2, 1);
    tt_c0frag_kernel<<<(NT * P0 + 3) / 4, 128>>>(c0);

    const int warps_per_block = 8;
    int blocks = (B + warps_per_block - 1) / warps_per_block;
    tt_lookup_kernel<<<blocks, warps_per_block * 32>>>(
        indices, offsets, (float*)d_out, B, bags_per_table);
}

// round 10
// speedup vs baseline: 2.1140x; 2.1140x over previous
#include <cuda_runtime.h>
#include <cuda_fp16.h>
#include <stdint.h>

#define NT 4
#define P0 100
#define P1C 100
#define P2C 100

// W12 scratch, per (t,i1,i2) slice as TWO mma.m16n8k16 A-fragments
// (k = r1 0..15 / 16..31). Slice = 1KB. 41 MB -> L2-resident.
__device__ __align__(16) __half g_W12[(size_t)NT * P1C * P2C * 512];

// c0 as fp16 B-fragments: per (t,i0) slice, lane l holds uint4
// {b0_f0, b1_f0, b0_f1, b1_f1}. B[k=r1][n=q0], cols 4..7 zero. 204.8KB.
__device__ uint4 g_c0f[(size_t)NT * P0 * 32];

// r = {hi:lo} packed fp16x2
__device__ __forceinline__ unsigned pack_h2(float lo, float hi) {
    unsigned r;
    asm("cvt.rn.f16x2.f32 %0, %1, %2;" : "=r"(r) : "f"(hi), "f"(lo));
    return r;
}

// ---------------------------------------------------------------------------
// Fused precompute. Blocks 0..399 = (t,i1): tensor-core GEMM
//   D[(i2,q2)][(q1,r1)] = sum_r2 c2[(i2,q2)][r2] * c1[r2][(q1,r1)]
// via m16n8k16 HMMA; A(c2)/B(c1) fp16 fragments built in smem; D written
// directly in the lookup's A-fragment layout with dense STG.128.
// Blocks 400..403: c0 -> B-fragments (one table each).
// ---------------------------------------------------------------------------
__global__ __launch_bounds__(256) void tt_precompute_kernel(
        const float* __restrict__ c1g, const float* __restrict__ c2g,
        const float* __restrict__ c0g) {
    int b = blockIdx.x;
    int tid = threadIdx.x;

    if (b >= NT * P1C) {                        // ---- c0 fragment blocks ----
        int tt = b - NT * P1C;
        for (int task = tid; task < P0 * 32; task += 256) {
            int sl = task >> 5, lane = task & 31;
            int g = lane >> 2, j = lane & 3;
            uint4 v = make_uint4(0u, 0u, 0u, 0u);
            if (g < 4) {
                const float* row = c0g + ((size_t)(tt * P0 + sl)) * 128 + g * 32 + 2 * j;
                float2 p0 = *(const float2*)(row);
                float2 p1 = *(const float2*)(row + 8);
                float2 p2 = *(const float2*)(row + 16);
                float2 p3 = *(const float2*)(row + 24);
                v.x = pack_h2(p0.x, p0.y);
                v.y = pack_h2(p1.x, p1.y);
                v.z = pack_h2(p2.x, p2.y);
                v.w = pack_h2(p3.x, p3.y);
            }
            g_c0f[(size_t)(tt * P0 + sl) * 32 + lane] = v;
        }
        return;
    }

    __shared__ uint4 smA[1600];   // A-frags: [mt 25][ks 2][lane 32], 25.6KB
    __shared__ uint4 smB[512];    // B-frags: [nt 16][lane 32], 8KB

    int t = b / P1C, i1 = b - t * P1C;

    // ---- Build A fragments from c2 table (per-table data, L2-hot) ----
    // A[(i2*4+q2)][r2] = c2[t][i2][r2][q2]; tile (mt,ks) rows 16mt.., k 16ks..
    const float* c2tab = c2g + (size_t)t * P2C * 128;
    for (int tau = tid; tau < 1600; tau += 256) {
        int mt = tau >> 6, ks = (tau >> 5) & 1, lane = tau & 31;
        int g = lane >> 2, tj = lane & 3;
        int i2a = 4 * mt + (g >> 2), q2 = g & 3;
        int kb = 16 * ks + 2 * tj;
        const float* pa = c2tab + i2a * 128 + q2;   // + r2*4 steps over r2
        const float* pb = pa + 2 * 128;             // i2b = i2a + 2 (rows +8)
        uint4 v;
        v.x = pack_h2(pa[kb * 4],       pa[(kb + 1) * 4]);
        v.y = pack_h2(pb[kb * 4],       pb[(kb + 1) * 4]);
        v.z = pack_h2(pa[(kb + 8) * 4], pa[(kb + 9) * 4]);
        v.w = pack_h2(pb[(kb + 8) * 4], pb[(kb + 9) * 4]);
        smA[tau] = v;
    }

    // ---- Build B fragments from this (t,i1)'s c1 slice ----
    // B[r2][(q1*32+r1)] = c1[r1][q1][r2]; col = 8nt+g -> c1 row (r1*4+q1),
    // contiguous over r2.
    const float* c1 = c1g + (size_t)(t * P1C + i1) * 4096;
    for (int tau = tid; tau < 512; tau += 256) {
        int nt = tau >> 5, lane = tau & 31;
        int g = lane >> 2, tj = lane & 3;
        int q1 = nt >> 2, r1 = 8 * (nt & 3) + g;
        const float* row = c1 + (r1 * 4 + q1) * 32;
        uint4 v;
        v.x = pack_h2(row[2 * tj],      row[2 * tj + 1]);
        v.y = pack_h2(row[2 * tj + 8],  row[2 * tj + 9]);
        v.z = pack_h2(row[2 * tj + 16], row[2 * tj + 17]);
        v.w = pack_h2(row[2 * tj + 24], row[2 * tj + 25]);
        smB[tau] = v;
    }
    __syncthreads();

    // ---- MMA: tasks (mt 0..24, quad 0..3); quad -> nt {nt0,nt0+8,nt0+1,nt0+9}
    // (nt0 = 2*quad) which fills regs 0..3 of one lookup lane-word. ----
    int w = tid >> 5, lane = tid & 31;
    int g3 = (lane >> 2) & 3, tj = lane & 3, ghi = lane >> 4;
    char* Wb = (char*)g_W12 + (size_t)(t * P1C + i1) * P2C * 1024;

    for (int tau = w; tau < 100; tau += 8) {
        int mt = tau >> 2, qd = tau & 3;
        int nt0 = 2 * qd, f = qd & 1, q1b = qd >> 1;
        uint4 A0 = smA[mt * 64 + lane];
        uint4 A1 = smA[mt * 64 + 32 + lane];
        unsigned pa[4], pb[4];
        const int nts[4] = {nt0, nt0 + 8, nt0 + 1, nt0 + 9};
        #pragma unroll
        for (int s = 0; s < 4; s++) {
            uint4 Bv = smB[nts[s] * 32 + lane];
            float d0 = 0.f, d1 = 0.f, d2 = 0.f, d3 = 0.f;
            asm volatile(
                "mma.sync.aligned.m16n8k16.row.col.f32.f16.f16.f32 "
                "{%0,%1,%2,%3}, {%4,%5,%6,%7}, {%8,%9}, {%0,%1,%2,%3};"
                : "+f"(d0), "+f"(d1), "+f"(d2), "+f"(d3)
                : "r"(A0.x), "r"(A0.y), "r"(A0.z), "r"(A0.w),
                  "r"(Bv.x), "r"(Bv.y));
            asm volatile(
                "mma.sync.aligned.m16n8k16.row.col.f32.f16.f16.f32 "
                "{%0,%1,%2,%3}, {%4,%5,%6,%7}, {%8,%9}, {%0,%1,%2,%3};"
                : "+f"(d0), "+f"(d1), "+f"(d2), "+f"(d3)
                : "r"(A1.x), "r"(A1.y), "r"(A1.z), "r"(A1.w),
                  "r"(Bv.z), "r"(Bv.w));
            pa[s] = pack_h2(d0, d1);     // rows g     -> slice i2_a
            pb[s] = pack_h2(d2, d3);     // rows g+8   -> slice i2_a + 2
        }
        // lane-word: lane' = (q1b*4 + g3)*4 + tj; slice i2_a = 4mt + ghi.
        size_t off = (size_t)(4 * mt + ghi) * 1024 + f * 512
                   + ((q1b * 4 + g3) * 4 + tj) * 16;
        *(uint4*)(Wb + off)        = make_uint4(pa[0], pa[1], pa[2], pa[3]);
        *(uint4*)(Wb + off + 2048) = make_uint4(pb[0], pb[1], pb[2], pb[3]);
    }
}

// ---------------------------------------------------------------------------
// Lookup + pool via HMMA. One warp per bag; at the chip LTS cap (~41us floor).
// ---------------------------------------------------------------------------
__global__ void tt_lookup_kernel(const int* __restrict__ indices,
                                 const int* __restrict__ offsets,
                                 float* __restrict__ out,
                                 int B, int bags_per_table) {
    int bag = (int)((blockIdx.x * (size_t)blockDim.x + threadIdx.x) >> 5);
    if (bag >= B) return;
    int lane = threadIdx.x & 31;
    int g = lane >> 2, j = lane & 3;

    int t = bag / bags_per_table;
    int s = offsets[bag], e = offsets[bag + 1];

    const uint4* Wt = (const uint4*)(g_W12 + (size_t)t * P1C * P2C * 512);
    const uint4* Cf = g_c0f + (size_t)t * P0 * 32;

    float d0 = 0.f, d1 = 0.f, d2 = 0.f, d3 = 0.f;

    for (int base = s; base < e; base += 32) {
        int n = min(32, e - base);
        int idx = (base + lane < e) ? indices[base + lane] : 0;  // coalesced
        int i0  = idx / 10000;
        int rem = idx - i0 * 10000;
        int v   = rem | (i0 << 20);

        for (int p = 0; p < n; p++) {
            int vp = __shfl_sync(0xffffffffu, v, p);
            const uint4* wb = Wt + (vp & 0xFFFFF) * 64;
            const uint4* cb = Cf + (vp >> 20) * 32;
            uint4 A0 = wb[lane];
            uint4 A1 = wb[32 + lane];
            uint4 Bf = cb[lane];
            asm volatile(
                "mma.sync.aligned.m16n8k16.row.col.f32.f16.f16.f32 "
                "{%0,%1,%2,%3}, {%4,%5,%6,%7}, {%8,%9}, {%0,%1,%2,%3};"
                : "+f"(d0), "+f"(d1), "+f"(d2), "+f"(d3)
                : "r"(A0.x), "r"(A0.y), "r"(A0.z), "r"(A0.w),
                  "r"(Bf.x), "r"(Bf.y));
            asm volatile(
                "mma.sync.aligned.m16n8k16.row.col.f32.f16.f16.f32 "
                "{%0,%1,%2,%3}, {%4,%5,%6,%7}, {%8,%9}, {%0,%1,%2,%3};"
                : "+f"(d0), "+f"(d1), "+f"(d2), "+f"(d3)
                : "r"(A1.x), "r"(A1.y), "r"(A1.z), "r"(A1.w),
                  "r"(Bf.z), "r"(Bf.w));
        }
    }

    if (j < 2) {
        float* ob = out + (size_t)bag * 64;
        ob[(2 * j) * 16 + g]         = d0;
        ob[(2 * j + 1) * 16 + g]     = d1;
        ob[(2 * j) * 16 + g + 8]     = d2;
        ob[(2 * j + 1) * 16 + g + 8] = d3;
    }
}

// ---------------------------------------------------------------------------
extern "C" void kernel_launch(void* const* d_in, const int* in_sizes, int n_in,
                              void* d_out, int out_size) {
    const int* indices = (const int*)d_in[0];
    const int* offsets = (const int*)d_in[1];
    const float* c0 = (const float*)d_in[2];
    const float* c1 = (const float*)d_in[3];
    const float* c2 = (const float*)d_in[4];

    int B = in_sizes[1] - 1;
    int bags_per_table = B / NT;

    tt_precompute_kernel<<<NT * P1C + NT, 256>>>(c1, c2, c0);

    const int warps_per_block = 8;
    int blocks = (B + warps_per_block - 1) / warps_per_block;
    tt_lookup_kernel<<<blocks, warps_per_block * 32>>>(
        indices, offsets, (float*)d_out, B, bags_per_table);
}